// round 14
// baseline (speedup 1.0000x reference)
#include <cuda_runtime.h>
#include <cuda_bf16.h>
#include <cstdint>

#define Bx 1024
#define Tx 512
#define Kx 64
#define WPB 7
#define GRID ((Bx + WPB - 1) / WPB)   // 147

// v rows: g_v[(b*511 + t)*32 + l] = (v_t[l], v_t[l+32]), t = 0..510
__device__ float2 g_v[(long)Bx * 511 * 32];
__device__ int g_last[Bx];

#define NEG_INF __int_as_float(0xff800000)

// Block: 14 warps. Warp w in [0,7): logZ for batch base+w.
//                  Warp w in [7,14): Viterbi for batch base+(w-7).
__global__ __launch_bounds__(14 * 32, 1) void crf_forward(
    const float* __restrict__ em, const int* __restrict__ mask,
    const float* __restrict__ trans, const float* __restrict__ startt,
    const float* __restrict__ endt, float* __restrict__ out)
{
    __shared__ float2 Tsm[32 * 32];          // T rows i in [32,64): (T[i][l], T[i][l+32])
    // E rows i in [32,64) as plain f32, paired (even i, odd i):
    // EL[ii*32+c] = (E[32+2ii][c],    E[32+2ii+1][c])
    // EH[ii*32+c] = (E[32+2ii][c+32], E[32+2ii+1][c+32])
    __shared__ __align__(8) float2 EL[16 * 32];
    __shared__ __align__(8) float2 EH[16 * 32];
    __shared__ __align__(8) float Ssm[WPB][Kx];   // logZ exchange
    __shared__ __align__(8) float Vsm[WPB][Kx];   // viterbi exchange
    __shared__ unsigned char maskb[WPB][Tx];

    const int tid = threadIdx.x;
    const int wid = tid >> 5;
    const int l = tid & 31;
    const int grp = (wid < WPB) ? wid : (wid - WPB);
    const bool is_logz = (wid < WPB);
    const int b = blockIdx.x * WPB + grp;
    const bool active = (b < Bx);

    // block-wide init of shared tables
    for (int idx = tid; idx < 32 * 32; idx += 14 * 32) {
        int r = idx >> 5, c = idx & 31;
        int i = r + 32;
        Tsm[idx] = make_float2(trans[i * Kx + c], trans[i * Kx + c + 32]);
    }
    for (int idx = tid; idx < 16 * 32; idx += 14 * 32) {
        int ii = idx >> 5, c = idx & 31;
        int i = 32 + 2 * ii;
        EL[idx] = make_float2(__expf(trans[i * Kx + c]),
                              __expf(trans[(i + 1) * Kx + c]));
        EH[idx] = make_float2(__expf(trans[i * Kx + c + 32]),
                              __expf(trans[(i + 1) * Kx + c + 32]));
    }
    if (is_logz && active) {
        for (int t = l; t < Tx; t += 32)
            maskb[grp][t] = (unsigned char)(mask[b * Tx + t] != 0);
    }
    __syncthreads();
    if (!active) return;

    const float* emp = em + (long)b * Tx * Kx;

    if (is_logz) {
        // ---------------- logZ warp: f32-E s-recurrence (no unpack LOPs) ----------------
        float er0[32], er1[32];              // E rows i in [0,32), plain f32
        #pragma unroll
        for (int i = 0; i < 32; ++i) {
            er0[i] = __expf(__ldg(trans + i * Kx + l));
            er1[i] = __expf(__ldg(trans + i * Kx + l + 32));
        }

        float s0 = __expf(startt[l] + emp[l]);
        float s1 = __expf(startt[l + 32] + emp[l + 32]);
        float L = 0.f;

        for (int t = 1; t < Tx; ++t) {
            const float e0 = __ldg(emp + t * Kx + l);
            const float e1 = __ldg(emp + t * Kx + l + 32);
            const float eem0 = __expf(e0);
            const float eem1 = __expf(e1);
            const int mt = maskb[grp][t];

            Ssm[grp][l] = s0;
            Ssm[grp][l + 32] = s1;
            __syncwarp();

            float acc0A = 0.f, acc0B = 0.f, acc1A = 0.f, acc1B = 0.f;
            // ---- i in [0,32): register-resident f32 E ----
            #pragma unroll
            for (int ii = 0; ii < 16; ++ii) {
                const float2 sp = *(const float2*)(&Ssm[grp][2 * ii]);
                acc0A += sp.x * er0[2 * ii];
                acc1A += sp.x * er1[2 * ii];
                acc0B += sp.y * er0[2 * ii + 1];
                acc1B += sp.y * er1[2 * ii + 1];
            }
            // ---- i in [32,64): smem-resident f32 E pairs ----
            #pragma unroll
            for (int ii = 0; ii < 16; ++ii) {
                const float2 sp = *(const float2*)(&Ssm[grp][32 + 2 * ii]);
                const float2 el = EL[ii * 32 + l];
                const float2 eh = EH[ii * 32 + l];
                acc0A += sp.x * el.x;
                acc1A += sp.x * eh.x;
                acc0B += sp.y * el.y;
                acc1B += sp.y * eh.y;
            }

            const float ns0 = (acc0A + acc0B) * eem0;
            const float ns1 = (acc1A + acc1B) * eem1;
            if (mt) { s0 = ns0; s1 = ns1; }

            if ((t & 3) == 0) {
                float c = __shfl_sync(0xffffffffu, s0, 0);
                float r = __fdividef(1.0f, c);
                s0 *= r; s1 *= r;
                L += __logf(c);
            }
            __syncwarp();
        }

        const float x0 = L + __logf(s0) + endt[l];
        const float x1 = L + __logf(s1) + endt[l + 32];
        float mm = fmaxf(x0, x1);
        #pragma unroll
        for (int o = 16; o; o >>= 1)
            mm = fmaxf(mm, __shfl_xor_sync(0xffffffffu, mm, o));
        float s = __expf(x0 - mm) + __expf(x1 - mm);
        #pragma unroll
        for (int o = 16; o; o >>= 1)
            s += __shfl_xor_sync(0xffffffffu, s, o);
        if (l == 0) out[b] = mm + __logf(s);
    } else {
        // ---------------- Viterbi warp: max-plus v-recurrence (bit-exact) ----------------
        float tr0[32], tr1[32];              // T rows i in [0,32)
        #pragma unroll
        for (int i = 0; i < 32; ++i) {
            tr0[i] = __ldg(trans + i * Kx + l);
            tr1[i] = __ldg(trans + i * Kx + l + 32);
        }

        float2* vout = g_v + (long)b * 511 * 32 + l;
        float v0 = startt[l] + emp[l];
        float v1 = startt[l + 32] + emp[l + 32];
        vout[0] = make_float2(v0, v1);

        for (int t = 1; t < Tx; ++t) {
            const float e0 = __ldg(emp + t * Kx + l);
            const float e1 = __ldg(emp + t * Kx + l + 32);
            const int mt = maskb[grp][t];

            Vsm[grp][l] = v0;
            Vsm[grp][l + 32] = v1;
            __syncwarp();

            float b0A = NEG_INF, b0B = NEG_INF, b1A = NEG_INF, b1B = NEG_INF;
            #pragma unroll
            for (int ii = 0; ii < 16; ++ii) {
                const float2 vp = *(const float2*)(&Vsm[grp][2 * ii]);
                b0A = fmaxf(b0A, vp.x + tr0[2 * ii]);
                b1A = fmaxf(b1A, vp.x + tr1[2 * ii]);
                b0B = fmaxf(b0B, vp.y + tr0[2 * ii + 1]);
                b1B = fmaxf(b1B, vp.y + tr1[2 * ii + 1]);
            }
            #pragma unroll
            for (int ii = 0; ii < 16; ++ii) {
                const float2 vp = *(const float2*)(&Vsm[grp][32 + 2 * ii]);
                const float2 ta = Tsm[(2 * ii) * 32 + l];
                const float2 tb = Tsm[(2 * ii + 1) * 32 + l];
                b0A = fmaxf(b0A, vp.x + ta.x);
                b1A = fmaxf(b1A, vp.x + ta.y);
                b0B = fmaxf(b0B, vp.y + tb.x);
                b1B = fmaxf(b1B, vp.y + tb.y);
            }

            const float nv0 = fmaxf(b0A, b0B) + e0;
            const float nv1 = fmaxf(b1A, b1B) + e1;
            if (mt) { v0 = nv0; v1 = nv1; }

            if (t < 511) vout[t * 32] = make_float2(v0, v1);
            __syncwarp();
        }

        // last tag: argmax(v + end), first-index tie-break
        Vsm[grp][l] = v0 + endt[l];
        Vsm[grp][l + 32] = v1 + endt[l + 32];
        __syncwarp();
        if (l == 0) {
            float bb = Vsm[grp][0]; int aa = 0;
            for (int i = 1; i < Kx; ++i) {
                float x = Vsm[grp][i];
                if (x > bb) { bb = x; aa = i; }
            }
            g_last[b] = aa;
        }
    }
}

// Monotone bijective float -> u32 key (total order identical to < on finite floats)
__device__ __forceinline__ unsigned int fkey(float f) {
    unsigned int u = __float_as_uint(f);
    return (u & 0x80000000u) ? ~u : (u | 0x80000000u);
}

#define BTW 8   // warps per backtrace block; each warp handles 2 batches

__global__ __launch_bounds__(BTW * 32) void crf_backtrace(
    const float* __restrict__ em, const int* __restrict__ tags,
    const int* __restrict__ mask, const float* __restrict__ trans,
    const float* __restrict__ startt, const float* __restrict__ endt,
    float* __restrict__ out)
{
    // Tt[c][l] = (T[l][c], T[l+32][c])  — transposed, paired
    __shared__ float2 Tt[Kx][32];
    __shared__ unsigned char path_s[2 * BTW][Tx];
    __shared__ unsigned char mk[2 * BTW][Tx];

    const int tid = threadIdx.x;
    const int w = tid >> 5;
    const int l = tid & 31;
    const int bA = blockIdx.x * (2 * BTW) + 2 * w;
    const int bB = bA + 1;
    const int sA = 2 * w, sB = 2 * w + 1;

    for (int idx = tid; idx < Kx * 32; idx += BTW * 32) {
        int c = idx >> 5, r = idx & 31;
        Tt[c][r] = make_float2(trans[r * Kx + c], trans[(r + 32) * Kx + c]);
    }
    for (int t = l; t < Tx; t += 32) {
        mk[sA][t] = (unsigned char)(mask[bA * Tx + t] != 0);
        mk[sB][t] = (unsigned char)(mask[bB * Tx + t] != 0);
    }
    __syncthreads();

    // ---- gold score for both batches (warp-parallel) ----
    #pragma unroll
    for (int p = 0; p < 2; ++p) {
        const int b = (p == 0) ? bA : bB;
        const int sl = (p == 0) ? sA : sB;
        float gp = 0.f; int cnt = 0;
        for (int t = l; t < Tx; t += 32) {
            int mkt = mk[sl][t];
            float mf = (float)mkt;
            cnt += mkt;
            int tg = tags[b * Tx + t];
            gp += em[((long)b * Tx + t) * Kx + tg] * mf;
            if (t > 0)
                gp += trans[tags[b * Tx + t - 1] * Kx + tg] * mf;
        }
        #pragma unroll
        for (int o = 16; o; o >>= 1) {
            gp  += __shfl_xor_sync(0xffffffffu, gp, o);
            cnt += __shfl_xor_sync(0xffffffffu, cnt, o);
        }
        if (l == 0) {
            int tg0 = tags[b * Tx];
            int tgl = tags[b * Tx + cnt - 1];
            out[b] = out[b] - (gp + startt[tg0] + endt[tgl]);  // nll
        }
    }

    // ---- dual-chain path recovery: two independent batches interleaved ----
    const float2* vrA = g_v + (long)bA * 511 * 32 + l;
    const float2* vrB = g_v + (long)bB * 511 * 32 + l;
    int curA = g_last[bA];
    int curB = g_last[bB];
    path_s[sA][Tx - 1] = (unsigned char)curA;
    path_s[sB][Tx - 1] = (unsigned char)curB;

    float2 ringA[8], ringB[8];
    #pragma unroll
    for (int k = 0; k < 8; ++k) {
        ringA[k] = __ldg(vrA + (510 - k) * 32);
        ringB[k] = __ldg(vrB + (510 - k) * 32);
    }

    #define BT_STEP2(S, VA, VB)                                              \
    {                                                                        \
        const int t_ = 511 - (S);                                            \
        float2 tpA = Tt[curA][l];                                            \
        float2 tpB = Tt[curB][l];                                            \
        unsigned int kA0 = fkey((VA).x + tpA.x);                             \
        unsigned int kA1 = fkey((VA).y + tpA.y);                             \
        unsigned int kB0 = fkey((VB).x + tpB.x);                             \
        unsigned int kB1 = fkey((VB).y + tpB.y);                             \
        unsigned int kmA = __reduce_max_sync(0xffffffffu,                    \
                                             kA0 > kA1 ? kA0 : kA1);         \
        unsigned int kmB = __reduce_max_sync(0xffffffffu,                    \
                                             kB0 > kB1 ? kB0 : kB1);         \
        unsigned int mA0 = __ballot_sync(0xffffffffu, kA0 == kmA);           \
        unsigned int mA1 = __ballot_sync(0xffffffffu, kA1 == kmA);           \
        unsigned int mB0 = __ballot_sync(0xffffffffu, kB0 == kmB);           \
        unsigned int mB1 = __ballot_sync(0xffffffffu, kB1 == kmB);           \
        int ncA = mA0 ? (__ffs(mA0) - 1) : (32 + __ffs(mA1) - 1);            \
        int ncB = mB0 ? (__ffs(mB0) - 1) : (32 + __ffs(mB1) - 1);            \
        curA = mk[sA][t_] ? ncA : curA;                                      \
        curB = mk[sB][t_] ? ncB : curB;                                      \
        path_s[sA][t_ - 1] = (unsigned char)curA;                            \
        path_s[sB][t_ - 1] = (unsigned char)curB;                            \
    }

    for (int s0 = 0; s0 < 504; s0 += 8) {
        #pragma unroll
        for (int k = 0; k < 8; ++k) {
            const int s = s0 + k;
            const float2 vA = ringA[k];
            const float2 vB = ringB[k];
            const int rp = 510 - (s + 8);           // row for step s+8
            const int rpc = (rp >= 0 ? rp : 0) * 32;
            ringA[k] = __ldg(vrA + rpc);
            ringB[k] = __ldg(vrB + rpc);
            BT_STEP2(s, vA, vB);
        }
    }
    #pragma unroll
    for (int k = 0; k < 7; ++k) {
        const int s = 504 + k;
        const float2 vA = ringA[k];
        const float2 vB = ringB[k];
        BT_STEP2(s, vA, vB);
    }
    #undef BT_STEP2

    __syncwarp();
    for (int t = l; t < Tx; t += 32) {
        out[Bx + (long)bA * Tx + t] = (float)path_s[sA][t];
        out[Bx + (long)bB * Tx + t] = (float)path_s[sB][t];
    }
}

extern "C" void kernel_launch(void* const* d_in, const int* in_sizes, int n_in,
                              void* d_out, int out_size)
{
    const float* em     = (const float*)d_in[0];
    const int*   tags   = (const int*)d_in[1];
    const int*   mask   = (const int*)d_in[2];
    const float* trans  = (const float*)d_in[3];
    const float* startt = (const float*)d_in[4];
    const float* endt   = (const float*)d_in[5];
    float* out = (float*)d_out;

    crf_forward<<<GRID, 14 * 32>>>(em, mask, trans, startt, endt, out);
    crf_backtrace<<<Bx / (2 * BTW), BTW * 32>>>(em, tags, mask, trans, startt, endt, out);
}

// round 15
// speedup vs baseline: 1.0233x; 1.0233x over previous
#include <cuda_runtime.h>
#include <cuda_bf16.h>
#include <cstdint>

#define Bx 1024
#define Tx 512
#define Kx 64
#define WPB 7
#define GRID ((Bx + WPB - 1) / WPB)   // 147

// v rows: g_v[(b*511 + t)*32 + l] = (v_t[l], v_t[l+32]), t = 0..510
__device__ float2 g_v[(long)Bx * 511 * 32];
__device__ int g_last[Bx];

#define NEG_INF __int_as_float(0xff800000)

// Block: 14 warps. Warp w in [0,7): logZ for batch base+w.
//                  Warp w in [7,14): Viterbi for batch base+(w-7).
__global__ __launch_bounds__(14 * 32, 1) void crf_forward(
    const float* __restrict__ em, const int* __restrict__ mask,
    const float* __restrict__ trans, const float* __restrict__ startt,
    const float* __restrict__ endt, float* __restrict__ out)
{
    __shared__ float2 Tsm[32 * 32];          // T rows i in [32,64): (T[i][l], T[i][l+32])
    __shared__ unsigned int Esm[32 * 32];    // E rows i in [32,64): bf16x2 (1-phase loads)
    __shared__ __align__(8) float Ssm[2][WPB][Kx];   // logZ exchange, ping-pong
    __shared__ __align__(8) float Vsm[2][WPB][Kx];   // viterbi exchange, ping-pong
    __shared__ unsigned char maskb[WPB][Tx];

    const int tid = threadIdx.x;
    const int wid = tid >> 5;
    const int l = tid & 31;
    const int grp = (wid < WPB) ? wid : (wid - WPB);
    const bool is_logz = (wid < WPB);
    const int b = blockIdx.x * WPB + grp;
    const bool active = (b < Bx);

    // block-wide init of shared tables
    for (int idx = tid; idx < 32 * 32; idx += 14 * 32) {
        int r = idx >> 5, c = idx & 31;
        int i = r + 32;
        float t0 = trans[i * Kx + c];
        float t1 = trans[i * Kx + c + 32];
        Tsm[idx] = make_float2(t0, t1);
        __nv_bfloat162 h = __float22bfloat162_rn(make_float2(__expf(t0), __expf(t1)));
        Esm[idx] = *reinterpret_cast<unsigned int*>(&h);
    }
    if (is_logz && active) {
        for (int t = l; t < Tx; t += 32)
            maskb[grp][t] = (unsigned char)(mask[b * Tx + t] != 0);
    }
    __syncthreads();
    if (!active) return;

    const float* emp = em + (long)b * Tx * Kx;

    if (is_logz) {
        // ---------------- logZ warp ----------------
        // reg half: E rows i in [0,32) as plain f32 (no unpack LOPs, 0 extra phases)
        float er0[32], er1[32];
        #pragma unroll
        for (int i = 0; i < 32; ++i) {
            er0[i] = __expf(__ldg(trans + i * Kx + l));
            er1[i] = __expf(__ldg(trans + i * Kx + l + 32));
        }

        float s0 = __expf(startt[l] + emp[l]);
        float s1 = __expf(startt[l + 32] + emp[l + 32]);
        float L = 0.f;

        for (int t = 1; t < Tx; ++t) {
            const float e0 = __ldg(emp + t * Kx + l);
            const float e1 = __ldg(emp + t * Kx + l + 32);
            const float eem0 = __expf(e0);
            const float eem1 = __expf(e1);
            const int mt = maskb[grp][t];
            const int pb = t & 1;

            Ssm[pb][grp][l] = s0;
            Ssm[pb][grp][l + 32] = s1;
            __syncwarp();

            float acc0A = 0.f, acc0B = 0.f, acc1A = 0.f, acc1B = 0.f;
            // ---- i in [0,32): register-resident f32 E ----
            #pragma unroll
            for (int ii = 0; ii < 16; ++ii) {
                const float2 sp = *(const float2*)(&Ssm[pb][grp][2 * ii]);
                acc0A += sp.x * er0[2 * ii];
                acc1A += sp.x * er1[2 * ii];
                acc0B += sp.y * er0[2 * ii + 1];
                acc1B += sp.y * er1[2 * ii + 1];
            }
            // ---- i in [32,64): smem bf16x2 (1-phase LDS.32 loads) ----
            #pragma unroll
            for (int ii = 0; ii < 16; ++ii) {
                const float2 sp = *(const float2*)(&Ssm[pb][grp][32 + 2 * ii]);
                {
                    unsigned int ep = Esm[(2 * ii) * 32 + l];
                    acc0A += sp.x * __uint_as_float(ep << 16);
                    acc1A += sp.x * __uint_as_float(ep & 0xffff0000u);
                }
                {
                    unsigned int ep = Esm[(2 * ii + 1) * 32 + l];
                    acc0B += sp.y * __uint_as_float(ep << 16);
                    acc1B += sp.y * __uint_as_float(ep & 0xffff0000u);
                }
            }

            const float ns0 = (acc0A + acc0B) * eem0;
            const float ns1 = (acc1A + acc1B) * eem1;
            if (mt) { s0 = ns0; s1 = ns1; }

            if ((t & 3) == 0) {
                float c = __shfl_sync(0xffffffffu, s0, 0);
                float r = __fdividef(1.0f, c);
                s0 *= r; s1 *= r;
                L += __logf(c);
            }
        }

        const float x0 = L + __logf(s0) + endt[l];
        const float x1 = L + __logf(s1) + endt[l + 32];
        float mm = fmaxf(x0, x1);
        #pragma unroll
        for (int o = 16; o; o >>= 1)
            mm = fmaxf(mm, __shfl_xor_sync(0xffffffffu, mm, o));
        float s = __expf(x0 - mm) + __expf(x1 - mm);
        #pragma unroll
        for (int o = 16; o; o >>= 1)
            s += __shfl_xor_sync(0xffffffffu, s, o);
        if (l == 0) out[b] = mm + __logf(s);
    } else {
        // ---------------- Viterbi warp: max-plus v-recurrence (bit-exact) ----------------
        float tr0[32], tr1[32];              // T rows i in [0,32)
        #pragma unroll
        for (int i = 0; i < 32; ++i) {
            tr0[i] = __ldg(trans + i * Kx + l);
            tr1[i] = __ldg(trans + i * Kx + l + 32);
        }

        float2* vout = g_v + (long)b * 511 * 32 + l;
        float v0 = startt[l] + emp[l];
        float v1 = startt[l + 32] + emp[l + 32];
        vout[0] = make_float2(v0, v1);

        for (int t = 1; t < Tx; ++t) {
            const float e0 = __ldg(emp + t * Kx + l);
            const float e1 = __ldg(emp + t * Kx + l + 32);
            const int mt = maskb[grp][t];
            const int pb = t & 1;

            Vsm[pb][grp][l] = v0;
            Vsm[pb][grp][l + 32] = v1;
            __syncwarp();

            // max is exact and associative — tree shape chosen to allow FMNMX3 fusion
            float b0R = NEG_INF, b1R = NEG_INF, b0S = NEG_INF, b1S = NEG_INF;
            #pragma unroll
            for (int ii = 0; ii < 16; ++ii) {
                const float2 vp = *(const float2*)(&Vsm[pb][grp][2 * ii]);
                b0R = fmaxf(fmaxf(b0R, vp.x + tr0[2 * ii]), vp.y + tr0[2 * ii + 1]);
                b1R = fmaxf(fmaxf(b1R, vp.x + tr1[2 * ii]), vp.y + tr1[2 * ii + 1]);
            }
            #pragma unroll
            for (int ii = 0; ii < 16; ++ii) {
                const float2 vp = *(const float2*)(&Vsm[pb][grp][32 + 2 * ii]);
                const float2 ta = Tsm[(2 * ii) * 32 + l];
                const float2 tb = Tsm[(2 * ii + 1) * 32 + l];
                b0S = fmaxf(fmaxf(b0S, vp.x + ta.x), vp.y + tb.x);
                b1S = fmaxf(fmaxf(b1S, vp.x + ta.y), vp.y + tb.y);
            }

            const float nv0 = fmaxf(b0R, b0S) + e0;
            const float nv1 = fmaxf(b1R, b1S) + e1;
            if (mt) { v0 = nv0; v1 = nv1; }

            if (t < 511) vout[t * 32] = make_float2(v0, v1);
        }

        // last tag: argmax(v + end), first-index tie-break
        Vsm[0][grp][l] = v0 + endt[l];
        Vsm[0][grp][l + 32] = v1 + endt[l + 32];
        __syncwarp();
        if (l == 0) {
            float bb = Vsm[0][grp][0]; int aa = 0;
            for (int i = 1; i < Kx; ++i) {
                float x = Vsm[0][grp][i];
                if (x > bb) { bb = x; aa = i; }
            }
            g_last[b] = aa;
        }
    }
}

// Monotone bijective float -> u32 key (total order identical to < on finite floats)
__device__ __forceinline__ unsigned int fkey(float f) {
    unsigned int u = __float_as_uint(f);
    return (u & 0x80000000u) ? ~u : (u | 0x80000000u);
}

#define BTW 8   // warps per backtrace block; each warp handles 2 batches

__global__ __launch_bounds__(BTW * 32) void crf_backtrace(
    const float* __restrict__ em, const int* __restrict__ tags,
    const int* __restrict__ mask, const float* __restrict__ trans,
    const float* __restrict__ startt, const float* __restrict__ endt,
    float* __restrict__ out)
{
    // Tt[c][l] = (T[l][c], T[l+32][c])  — transposed, paired
    __shared__ float2 Tt[Kx][32];
    __shared__ unsigned char path_s[2 * BTW][Tx];
    __shared__ unsigned char mk[2 * BTW][Tx];

    const int tid = threadIdx.x;
    const int w = tid >> 5;
    const int l = tid & 31;
    const int bA = blockIdx.x * (2 * BTW) + 2 * w;
    const int bB = bA + 1;
    const int sA = 2 * w, sB = 2 * w + 1;

    for (int idx = tid; idx < Kx * 32; idx += BTW * 32) {
        int c = idx >> 5, r = idx & 31;
        Tt[c][r] = make_float2(trans[r * Kx + c], trans[(r + 32) * Kx + c]);
    }
    for (int t = l; t < Tx; t += 32) {
        mk[sA][t] = (unsigned char)(mask[bA * Tx + t] != 0);
        mk[sB][t] = (unsigned char)(mask[bB * Tx + t] != 0);
    }
    __syncthreads();

    // ---- gold score for both batches (warp-parallel) ----
    #pragma unroll
    for (int p = 0; p < 2; ++p) {
        const int b = (p == 0) ? bA : bB;
        const int sl = (p == 0) ? sA : sB;
        float gp = 0.f; int cnt = 0;
        for (int t = l; t < Tx; t += 32) {
            int mkt = mk[sl][t];
            float mf = (float)mkt;
            cnt += mkt;
            int tg = tags[b * Tx + t];
            gp += em[((long)b * Tx + t) * Kx + tg] * mf;
            if (t > 0)
                gp += trans[tags[b * Tx + t - 1] * Kx + tg] * mf;
        }
        #pragma unroll
        for (int o = 16; o; o >>= 1) {
            gp  += __shfl_xor_sync(0xffffffffu, gp, o);
            cnt += __shfl_xor_sync(0xffffffffu, cnt, o);
        }
        if (l == 0) {
            int tg0 = tags[b * Tx];
            int tgl = tags[b * Tx + cnt - 1];
            out[b] = out[b] - (gp + startt[tg0] + endt[tgl]);  // nll
        }
    }

    // ---- dual-chain path recovery: two independent batches interleaved ----
    const float2* vrA = g_v + (long)bA * 511 * 32 + l;
    const float2* vrB = g_v + (long)bB * 511 * 32 + l;
    int curA = g_last[bA];
    int curB = g_last[bB];
    path_s[sA][Tx - 1] = (unsigned char)curA;
    path_s[sB][Tx - 1] = (unsigned char)curB;

    float2 ringA[8], ringB[8];
    #pragma unroll
    for (int k = 0; k < 8; ++k) {
        ringA[k] = __ldg(vrA + (510 - k) * 32);
        ringB[k] = __ldg(vrB + (510 - k) * 32);
    }

    #define BT_STEP2(S, VA, VB)                                              \
    {                                                                        \
        const int t_ = 511 - (S);                                            \
        float2 tpA = Tt[curA][l];                                            \
        float2 tpB = Tt[curB][l];                                            \
        unsigned int kA0 = fkey((VA).x + tpA.x);                             \
        unsigned int kA1 = fkey((VA).y + tpA.y);                             \
        unsigned int kB0 = fkey((VB).x + tpB.x);                             \
        unsigned int kB1 = fkey((VB).y + tpB.y);                             \
        unsigned int kmA = __reduce_max_sync(0xffffffffu,                    \
                                             kA0 > kA1 ? kA0 : kA1);         \
        unsigned int kmB = __reduce_max_sync(0xffffffffu,                    \
                                             kB0 > kB1 ? kB0 : kB1);         \
        unsigned int mA0 = __ballot_sync(0xffffffffu, kA0 == kmA);           \
        unsigned int mA1 = __ballot_sync(0xffffffffu, kA1 == kmA);           \
        unsigned int mB0 = __ballot_sync(0xffffffffu, kB0 == kmB);           \
        unsigned int mB1 = __ballot_sync(0xffffffffu, kB1 == kmB);           \
        int ncA = mA0 ? (__ffs(mA0) - 1) : (32 + __ffs(mA1) - 1);            \
        int ncB = mB0 ? (__ffs(mB0) - 1) : (32 + __ffs(mB1) - 1);            \
        curA = mk[sA][t_] ? ncA : curA;                                      \
        curB = mk[sB][t_] ? ncB : curB;                                      \
        path_s[sA][t_ - 1] = (unsigned char)curA;                            \
        path_s[sB][t_ - 1] = (unsigned char)curB;                            \
    }

    for (int s0 = 0; s0 < 504; s0 += 8) {
        #pragma unroll
        for (int k = 0; k < 8; ++k) {
            const int s = s0 + k;
            const float2 vA = ringA[k];
            const float2 vB = ringB[k];
            const int rp = 510 - (s + 8);           // row for step s+8
            const int rpc = (rp >= 0 ? rp : 0) * 32;
            ringA[k] = __ldg(vrA + rpc);
            ringB[k] = __ldg(vrB + rpc);
            BT_STEP2(s, vA, vB);
        }
    }
    #pragma unroll
    for (int k = 0; k < 7; ++k) {
        const int s = 504 + k;
        const float2 vA = ringA[k];
        const float2 vB = ringB[k];
        BT_STEP2(s, vA, vB);
    }
    #undef BT_STEP2

    __syncwarp();
    for (int t = l; t < Tx; t += 32) {
        out[Bx + (long)bA * Tx + t] = (float)path_s[sA][t];
        out[Bx + (long)bB * Tx + t] = (float)path_s[sB][t];
    }
}

extern "C" void kernel_launch(void* const* d_in, const int* in_sizes, int n_in,
                              void* d_out, int out_size)
{
    const float* em     = (const float*)d_in[0];
    const int*   tags   = (const int*)d_in[1];
    const int*   mask   = (const int*)d_in[2];
    const float* trans  = (const float*)d_in[3];
    const float* startt = (const float*)d_in[4];
    const float* endt   = (const float*)d_in[5];
    float* out = (float*)d_out;

    crf_forward<<<GRID, 14 * 32>>>(em, mask, trans, startt, endt, out);
    crf_backtrace<<<Bx / (2 * BTW), BTW * 32>>>(em, tags, mask, trans, startt, endt, out);
}

// round 16
// speedup vs baseline: 1.0669x; 1.0426x over previous
#include <cuda_runtime.h>
#include <cuda_bf16.h>
#include <cstdint>

#define Bx 1024
#define Tx 512
#define Kx 64
#define WPB 7
#define GRID ((Bx + WPB - 1) / WPB)   // 147

// v rows: g_v[(b*511 + t)*32 + l] = (v_t[l], v_t[l+32]), t = 0..510
__device__ float2 g_v[(long)Bx * 511 * 32];
__device__ int g_last[Bx];

#define NEG_INF __int_as_float(0xff800000)

// Block: 14 warps. Warp w in [0,7): logZ for batch base+w.
//                  Warp w in [7,14): Viterbi for batch base+(w-7).
__global__ __launch_bounds__(14 * 32, 1) void crf_forward(
    const float* __restrict__ em, const int* __restrict__ mask,
    const float* __restrict__ trans, const float* __restrict__ startt,
    const float* __restrict__ endt, float* __restrict__ out)
{
    __shared__ float2 Tsm[32 * 32];          // T rows i in [32,64): (T[i][l], T[i][l+32])
    __shared__ unsigned int Esm[32 * 32];    // E rows i in [32,64): bf16x2
    __shared__ __align__(8) float Ssm[WPB][Kx];   // logZ exchange
    __shared__ __align__(8) float Vsm[WPB][Kx];   // viterbi exchange
    __shared__ unsigned char maskb[WPB][Tx];

    const int tid = threadIdx.x;
    const int wid = tid >> 5;
    const int l = tid & 31;
    const int grp = (wid < WPB) ? wid : (wid - WPB);
    const bool is_logz = (wid < WPB);
    const int b = blockIdx.x * WPB + grp;
    const bool active = (b < Bx);

    // block-wide init of shared tables
    for (int idx = tid; idx < 32 * 32; idx += 14 * 32) {
        int r = idx >> 5, c = idx & 31;
        int i = r + 32;
        float t0 = trans[i * Kx + c];
        float t1 = trans[i * Kx + c + 32];
        Tsm[idx] = make_float2(t0, t1);
        __nv_bfloat162 h = __float22bfloat162_rn(make_float2(__expf(t0), __expf(t1)));
        Esm[idx] = *reinterpret_cast<unsigned int*>(&h);
    }
    if (is_logz && active) {
        for (int t = l; t < Tx; t += 32)
            maskb[grp][t] = (unsigned char)(mask[b * Tx + t] != 0);
    }
    __syncthreads();
    if (!active) return;

    const float* emp = em + (long)b * Tx * Kx;

    if (is_logz) {
        // ---------------- logZ warp: linear-domain s-recurrence ----------------
        unsigned int ee[32];                 // E rows i in [0,32) as bf16x2
        #pragma unroll
        for (int i = 0; i < 32; ++i) {
            float t0 = trans[i * Kx + l];
            float t1 = trans[i * Kx + l + 32];
            __nv_bfloat162 h = __float22bfloat162_rn(
                make_float2(__expf(t0), __expf(t1)));
            ee[i] = *reinterpret_cast<unsigned int*>(&h);
        }

        float s0 = __expf(startt[l] + emp[l]);
        float s1 = __expf(startt[l + 32] + emp[l + 32]);
        float L = 0.f;

        for (int t = 1; t < Tx; ++t) {
            const float e0 = __ldg(emp + t * Kx + l);
            const float e1 = __ldg(emp + t * Kx + l + 32);
            const float eem0 = __expf(e0);
            const float eem1 = __expf(e1);
            const int mt = maskb[grp][t];

            Ssm[grp][l] = s0;
            Ssm[grp][l + 32] = s1;
            __syncwarp();

            float acc0A = 0.f, acc0B = 0.f, acc1A = 0.f, acc1B = 0.f;
            #pragma unroll
            for (int ii = 0; ii < 16; ++ii) {
                const float2 sp = *(const float2*)(&Ssm[grp][2 * ii]);
                {
                    unsigned int ep = ee[2 * ii];
                    acc0A += sp.x * __uint_as_float(ep << 16);
                    acc1A += sp.x * __uint_as_float(ep & 0xffff0000u);
                }
                {
                    unsigned int ep = ee[2 * ii + 1];
                    acc0B += sp.y * __uint_as_float(ep << 16);
                    acc1B += sp.y * __uint_as_float(ep & 0xffff0000u);
                }
            }
            #pragma unroll
            for (int ii = 0; ii < 16; ++ii) {
                const float2 sp = *(const float2*)(&Ssm[grp][32 + 2 * ii]);
                {
                    unsigned int ep = Esm[(2 * ii) * 32 + l];
                    acc0A += sp.x * __uint_as_float(ep << 16);
                    acc1A += sp.x * __uint_as_float(ep & 0xffff0000u);
                }
                {
                    unsigned int ep = Esm[(2 * ii + 1) * 32 + l];
                    acc0B += sp.y * __uint_as_float(ep << 16);
                    acc1B += sp.y * __uint_as_float(ep & 0xffff0000u);
                }
            }

            const float ns0 = (acc0A + acc0B) * eem0;
            const float ns1 = (acc1A + acc1B) * eem1;
            if (mt) { s0 = ns0; s1 = ns1; }

            if ((t & 3) == 0) {
                float c = __shfl_sync(0xffffffffu, s0, 0);
                float r = __fdividef(1.0f, c);
                s0 *= r; s1 *= r;
                L += __logf(c);
            }
            __syncwarp();
        }

        const float x0 = L + __logf(s0) + endt[l];
        const float x1 = L + __logf(s1) + endt[l + 32];
        float mm = fmaxf(x0, x1);
        #pragma unroll
        for (int o = 16; o; o >>= 1)
            mm = fmaxf(mm, __shfl_xor_sync(0xffffffffu, mm, o));
        float s = __expf(x0 - mm) + __expf(x1 - mm);
        #pragma unroll
        for (int o = 16; o; o >>= 1)
            s += __shfl_xor_sync(0xffffffffu, s, o);
        if (l == 0) out[b] = mm + __logf(s);
    } else {
        // ---------------- Viterbi warp: max-plus v-recurrence (bit-exact) ----------------
        float tr0[32], tr1[32];              // T rows i in [0,32)
        #pragma unroll
        for (int i = 0; i < 32; ++i) {
            tr0[i] = __ldg(trans + i * Kx + l);
            tr1[i] = __ldg(trans + i * Kx + l + 32);
        }

        float2* vout = g_v + (long)b * 511 * 32 + l;
        float v0 = startt[l] + emp[l];
        float v1 = startt[l + 32] + emp[l + 32];
        vout[0] = make_float2(v0, v1);

        for (int t = 1; t < Tx; ++t) {
            const float e0 = __ldg(emp + t * Kx + l);
            const float e1 = __ldg(emp + t * Kx + l + 32);
            const int mt = maskb[grp][t];

            Vsm[grp][l] = v0;
            Vsm[grp][l + 32] = v1;
            __syncwarp();

            float b0A = NEG_INF, b0B = NEG_INF, b1A = NEG_INF, b1B = NEG_INF;
            #pragma unroll
            for (int ii = 0; ii < 16; ++ii) {
                const float2 vp = *(const float2*)(&Vsm[grp][2 * ii]);
                b0A = fmaxf(b0A, vp.x + tr0[2 * ii]);
                b1A = fmaxf(b1A, vp.x + tr1[2 * ii]);
                b0B = fmaxf(b0B, vp.y + tr0[2 * ii + 1]);
                b1B = fmaxf(b1B, vp.y + tr1[2 * ii + 1]);
            }
            #pragma unroll
            for (int ii = 0; ii < 16; ++ii) {
                const float2 vp = *(const float2*)(&Vsm[grp][32 + 2 * ii]);
                const float2 ta = Tsm[(2 * ii) * 32 + l];
                const float2 tb = Tsm[(2 * ii + 1) * 32 + l];
                b0A = fmaxf(b0A, vp.x + ta.x);
                b1A = fmaxf(b1A, vp.x + ta.y);
                b0B = fmaxf(b0B, vp.y + tb.x);
                b1B = fmaxf(b1B, vp.y + tb.y);
            }

            const float nv0 = fmaxf(b0A, b0B) + e0;
            const float nv1 = fmaxf(b1A, b1B) + e1;
            if (mt) { v0 = nv0; v1 = nv1; }

            if (t < 511) vout[t * 32] = make_float2(v0, v1);
            __syncwarp();
        }

        // last tag: argmax(v + end), first-index tie-break
        Vsm[grp][l] = v0 + endt[l];
        Vsm[grp][l + 32] = v1 + endt[l + 32];
        __syncwarp();
        if (l == 0) {
            float bb = Vsm[grp][0]; int aa = 0;
            for (int i = 1; i < Kx; ++i) {
                float x = Vsm[grp][i];
                if (x > bb) { bb = x; aa = i; }
            }
            g_last[b] = aa;
        }
    }
}

// Monotone bijective float -> u32 key, branchless (SHF + LOP3, no predicates).
// Total order identical to < on finite floats; equal floats -> equal keys.
__device__ __forceinline__ unsigned int fkey(float f) {
    unsigned int u = __float_as_uint(f);
    return u ^ (((unsigned int)(((int)u) >> 31)) | 0x80000000u);
}

#define BTW 8   // warps per backtrace block; each warp handles 2 batches

__global__ __launch_bounds__(BTW * 32) void crf_backtrace(
    const float* __restrict__ em, const int* __restrict__ tags,
    const int* __restrict__ mask, const float* __restrict__ trans,
    const float* __restrict__ startt, const float* __restrict__ endt,
    float* __restrict__ out)
{
    // Tt[c][l] = (T[l][c], T[l+32][c])  — transposed, paired
    __shared__ float2 Tt[Kx][32];
    __shared__ unsigned char path_s[2 * BTW][Tx];
    __shared__ __align__(8) unsigned char mk[2 * BTW][Tx];

    const int tid = threadIdx.x;
    const int w = tid >> 5;
    const int l = tid & 31;
    const int bA = blockIdx.x * (2 * BTW) + 2 * w;
    const int bB = bA + 1;
    const int sA = 2 * w, sB = 2 * w + 1;

    for (int idx = tid; idx < Kx * 32; idx += BTW * 32) {
        int c = idx >> 5, r = idx & 31;
        Tt[c][r] = make_float2(trans[r * Kx + c], trans[(r + 32) * Kx + c]);
    }
    for (int t = l; t < Tx; t += 32) {
        mk[sA][t] = (unsigned char)(mask[bA * Tx + t] != 0);
        mk[sB][t] = (unsigned char)(mask[bB * Tx + t] != 0);
    }
    __syncthreads();

    // ---- gold score for both batches (warp-parallel) ----
    #pragma unroll
    for (int p = 0; p < 2; ++p) {
        const int b = (p == 0) ? bA : bB;
        const int sl = (p == 0) ? sA : sB;
        float gp = 0.f; int cnt = 0;
        for (int t = l; t < Tx; t += 32) {
            int mkt = mk[sl][t];
            float mf = (float)mkt;
            cnt += mkt;
            int tg = tags[b * Tx + t];
            gp += em[((long)b * Tx + t) * Kx + tg] * mf;
            if (t > 0)
                gp += trans[tags[b * Tx + t - 1] * Kx + tg] * mf;
        }
        #pragma unroll
        for (int o = 16; o; o >>= 1) {
            gp  += __shfl_xor_sync(0xffffffffu, gp, o);
            cnt += __shfl_xor_sync(0xffffffffu, cnt, o);
        }
        if (l == 0) {
            int tg0 = tags[b * Tx];
            int tgl = tags[b * Tx + cnt - 1];
            out[b] = out[b] - (gp + startt[tg0] + endt[tgl]);  // nll
        }
    }

    // ---- dual-chain path recovery: 2 collectives per step, mask bits hoisted ----
    const float2* vrA = g_v + (long)bA * 511 * 32 + l;
    const float2* vrB = g_v + (long)bB * 511 * 32 + l;
    int curA = g_last[bA];
    int curB = g_last[bB];
    path_s[sA][Tx - 1] = (unsigned char)curA;
    path_s[sB][Tx - 1] = (unsigned char)curB;

    float2 ringA[8], ringB[8];
    #pragma unroll
    for (int k = 0; k < 8; ++k) {
        ringA[k] = __ldg(vrA + (510 - k) * 32);
        ringB[k] = __ldg(vrB + (510 - k) * 32);
    }

    // step s: t_ = 511-s. mask byte for step s0+k lives at byte (7-k) of the
    // u64 loaded from &mk[..][504-s0] (aligned: s0 % 8 == 0).
    #define BT_STEP2(S, K7, VA, VB, MKA, MKB)                                \
    {                                                                        \
        const int t_ = 511 - (S);                                            \
        float2 tpA = Tt[curA][l];                                            \
        float2 tpB = Tt[curB][l];                                            \
        unsigned int kA0 = fkey((VA).x + tpA.x);                             \
        unsigned int kA1 = fkey((VA).y + tpA.y);                             \
        unsigned int kB0 = fkey((VB).x + tpB.x);                             \
        unsigned int kB1 = fkey((VB).y + tpB.y);                             \
        unsigned int kmA = __reduce_max_sync(0xffffffffu,                    \
                                             kA0 > kA1 ? kA0 : kA1);         \
        unsigned int kmB = __reduce_max_sync(0xffffffffu,                    \
                                             kB0 > kB1 ? kB0 : kB1);         \
        int candA = (kA0 == kmA) ? l : ((kA1 == kmA) ? (32 + l) : 64);       \
        int candB = (kB0 == kmB) ? l : ((kB1 == kmB) ? (32 + l) : 64);       \
        int ncA = __reduce_min_sync(0xffffffffu, candA);                     \
        int ncB = __reduce_min_sync(0xffffffffu, candB);                     \
        curA = ((MKA >> ((K7) * 8)) & 1ull) ? ncA : curA;                    \
        curB = ((MKB >> ((K7) * 8)) & 1ull) ? ncB : curB;                    \
        path_s[sA][t_ - 1] = (unsigned char)curA;                            \
        path_s[sB][t_ - 1] = (unsigned char)curB;                            \
    }

    for (int s0 = 0; s0 < 504; s0 += 8) {
        const unsigned long long mkA =
            *(const unsigned long long*)(&mk[sA][504 - s0]);
        const unsigned long long mkB =
            *(const unsigned long long*)(&mk[sB][504 - s0]);
        #pragma unroll
        for (int k = 0; k < 8; ++k) {
            const int s = s0 + k;
            const float2 vA = ringA[k];
            const float2 vB = ringB[k];
            const int rp = 510 - (s + 8);           // row for step s+8
            const int rpc = (rp >= 0 ? rp : 0) * 32;
            ringA[k] = __ldg(vrA + rpc);
            ringB[k] = __ldg(vrB + rpc);
            BT_STEP2(s, 7 - k, vA, vB, mkA, mkB);
        }
    }
    {
        // epilogue: s = 504..510, t_ = 7..1; mask bytes at mk[..][0..7]
        const unsigned long long mkA = *(const unsigned long long*)(&mk[sA][0]);
        const unsigned long long mkB = *(const unsigned long long*)(&mk[sB][0]);
        #pragma unroll
        for (int k = 0; k < 7; ++k) {
            const int s = 504 + k;
            const float2 vA = ringA[k];
            const float2 vB = ringB[k];
            BT_STEP2(s, 7 - k, vA, vB, mkA, mkB);
        }
    }
    #undef BT_STEP2

    __syncwarp();
    for (int t = l; t < Tx; t += 32) {
        out[Bx + (long)bA * Tx + t] = (float)path_s[sA][t];
        out[Bx + (long)bB * Tx + t] = (float)path_s[sB][t];
    }
}

extern "C" void kernel_launch(void* const* d_in, const int* in_sizes, int n_in,
                              void* d_out, int out_size)
{
    const float* em     = (const float*)d_in[0];
    const int*   tags   = (const int*)d_in[1];
    const int*   mask   = (const int*)d_in[2];
    const float* trans  = (const float*)d_in[3];
    const float* startt = (const float*)d_in[4];
    const float* endt   = (const float*)d_in[5];
    float* out = (float*)d_out;

    crf_forward<<<GRID, 14 * 32>>>(em, mask, trans, startt, endt, out);
    crf_backtrace<<<Bx / (2 * BTW), BTW * 32>>>(em, tags, mask, trans, startt, endt, out);
}